// round 10
// baseline (speedup 1.0000x reference)
#include <cuda_runtime.h>
#include <cuda_bf16.h>
#include <cooperative_groups.h>
#include <math.h>

namespace cg = cooperative_groups;

// Fixed problem dims
#define BB   128
#define TT   255
#define NN   256
#define HH   256
#define FH   1024
#define MM   (BB*TT)          // 32640

// Static device scratch (no allocations allowed)
__device__ float g_alpha[BB * NN];
__device__ float g_P[(size_t)MM * FH];   // 133.7 MB

// ---------------------------------------------------------------------------
// helpers
// ---------------------------------------------------------------------------
__device__ __forceinline__ uint32_t smem_u32(const void* p) {
    uint32_t a;
    asm("{ .reg .u64 t; cvta.to.shared.u64 t, %1; cvt.u32.u64 %0, t; }"
        : "=r"(a) : "l"(p));
    return a;
}
__device__ __forceinline__ uint32_t mapa_u32(uint32_t addr, uint32_t rank) {
    uint32_t r;
    asm("mapa.shared::cluster.u32 %0, %1, %2;" : "=r"(r) : "r"(addr), "r"(rank));
    return r;
}
__device__ __forceinline__ void ffma2(unsigned long long& d,
                                      unsigned long long a,
                                      unsigned long long b) {
    asm("fma.rn.f32x2 %0, %1, %2, %0;" : "+l"(d) : "l"(a), "l"(b));
}
__device__ __forceinline__ float pairsum(unsigned long long v) {
    float lo, hi;
    asm("mov.b64 {%0,%1}, %2;" : "=f"(lo), "=f"(hi) : "l"(v));
    return lo + hi;
}
__device__ __forceinline__ unsigned long long pack2(float a) {
    unsigned long long d;
    asm("mov.b64 %0, {%1,%1};" : "=l"(d) : "f"(a));
    return d;
}
__device__ __forceinline__ void unpack2(unsigned long long v, float& lo, float& hi) {
    asm("mov.b64 {%0,%1}, %2;" : "=f"(lo), "=f"(hi) : "l"(v));
}
__device__ __forceinline__ void mbar_init(uint32_t mbar, uint32_t count) {
    asm volatile("mbarrier.init.shared.b64 [%0], %1;" :: "r"(mbar), "r"(count)
                 : "memory");
}
__device__ __forceinline__ void mbar_arm_tx(uint32_t mbar, uint32_t tx) {
    asm volatile("mbarrier.arrive.expect_tx.shared.b64 _, [%0], %1;"
                 :: "r"(mbar), "r"(tx) : "memory");
}
__device__ __forceinline__ void mbar_wait_acq(uint32_t mbar, uint32_t parity) {
    uint32_t done;
    asm volatile(
        "{\n\t.reg .pred P;\n\t"
        "mbarrier.try_wait.parity.acquire.cluster.shared::cta.b64 P, [%1], %2;\n\t"
        "selp.b32 %0, 1, 0, P;\n\t}"
        : "=r"(done) : "r"(mbar), "r"(parity) : "memory");
    while (!done) {
        asm volatile(
            "{\n\t.reg .pred P;\n\t"
            "mbarrier.try_wait.parity.acquire.cluster.shared::cta.b64 P, [%1], %2, 0x989680;\n\t"
            "selp.b32 %0, 1, 0, P;\n\t}"
            : "=r"(done) : "r"(mbar), "r"(parity) : "memory");
    }
}
// DSMEM bulk copy: local smem -> remote CTA smem, tx-counted on remote mbar.
__device__ __forceinline__ void bulk_dsmem(uint32_t dst_remote, uint32_t src_local,
                                           uint32_t bytes, uint32_t remote_mbar) {
    asm volatile(
        "cp.async.bulk.shared::cluster.shared::cta.mbarrier::complete_tx::bytes "
        "[%0], [%1], %2, [%3];"
        :: "r"(dst_remote), "r"(src_local), "r"(bytes), "r"(remote_mbar)
        : "memory");
}
__device__ __forceinline__ void fence_async_proxy() {
    asm volatile("fence.proxy.async.shared::cta;" ::: "memory");
}
__device__ __forceinline__ float sigf(float x) {
    return __fdividef(1.0f, 1.0f + __expf(-x));
}
__device__ __forceinline__ float tanh_fast(float x) {
    float e = __expf(-2.0f * x);
    return __fdividef(1.0f - e, 1.0f + e);
}

// ---------------------------------------------------------------------------
// K1: alpha[b,n] = softmax_n( b_attn + sum_t X[b,t,n] * Wa[2H+t] )
// ---------------------------------------------------------------------------
__global__ __launch_bounds__(256) void k_alpha(const float* __restrict__ X,
                                               const float* __restrict__ Wa,
                                               const float* __restrict__ ba) {
    __shared__ float was[TT];
    __shared__ float red[256];
    const int b = blockIdx.x, n = threadIdx.x;
    if (n < TT) was[n] = Wa[2 * HH + n];
    __syncthreads();

    const float* xb = X + (size_t)b * TT * NN + n;
    float acc = ba[0];
#pragma unroll 5
    for (int t = 0; t < TT; ++t) acc = fmaf(xb[(size_t)t * NN], was[t], acc);

    red[n] = acc; __syncthreads();
    for (int s = 128; s > 0; s >>= 1) {
        if (n < s) red[n] = fmaxf(red[n], red[n + s]);
        __syncthreads();
    }
    const float mx = red[0]; __syncthreads();
    const float e = expf(acc - mx);
    red[n] = e; __syncthreads();
    for (int s = 128; s > 0; s >>= 1) {
        if (n < s) red[n] += red[n + s];
        __syncthreads();
    }
    g_alpha[b * NN + n] = e / red[0];
}

// ---------------------------------------------------------------------------
// K2: X_tilde = alpha * X  ->  d_out[0 : MM*NN)
// ---------------------------------------------------------------------------
__global__ __launch_bounds__(256) void k_xtilde(const float* __restrict__ X,
                                                float* __restrict__ out) {
    const int idx = blockIdx.x * 256 + threadIdx.x;          // < MM*NN/4
    const float4 x = ((const float4*)X)[idx];
    const int b   = idx / (TT * NN / 4);
    const int rem = idx - b * (TT * NN / 4);
    const int n4  = rem & (NN / 4 - 1);
    const float4 a = ((const float4*)g_alpha)[b * (NN / 4) + n4];
    float4 o;
    o.x = x.x * a.x; o.y = x.y * a.y; o.z = x.z * a.z; o.w = x.w * a.w;
    ((float4*)out)[idx] = o;
}

// ---------------------------------------------------------------------------
// K3: P = X_tilde @ W_lstm + b_lstm   (M=32640, Ncols=1024, K=256) fp32
// 128x128 tile, 256 threads, 8x8 microtile, fma.rn.f32x2,
// register double-buffered global loads.
// ---------------------------------------------------------------------------
__global__ __launch_bounds__(256) void k_gemm(const float* __restrict__ A,
                                              const float* __restrict__ W,
                                              const float* __restrict__ bias) {
    __shared__ float As[16 * 132];
    __shared__ float Bs[16 * 132];
    const int tx = threadIdx.x & 15;
    const int ty = threadIdx.x >> 4;
    const int m0 = blockIdx.y * 128;
    const int c0 = blockIdx.x * 128;

    unsigned long long acc2[8][4];
#pragma unroll
    for (int i = 0; i < 8; ++i)
#pragma unroll
        for (int j = 0; j < 4; ++j) acc2[i][j] = 0ull;

    float4 pa[2], pb[2];
#pragma unroll
    for (int i = 0; i < 2; ++i) {
        const int id = threadIdx.x + 256 * i;
        pa[i] = *(const float4*)(A + (size_t)(m0 + (id >> 2)) * 256 + 4 * (id & 3));
        pb[i] = *(const float4*)(W + (size_t)(id >> 5) * 1024 + c0 + 4 * (id & 31));
    }

    for (int kk0 = 0; kk0 < 256; kk0 += 16) {
#pragma unroll
        for (int i = 0; i < 2; ++i) {               // store staged tiles
            const int id = threadIdx.x + 256 * i;
            const int q = id & 3, row = id >> 2;
            As[(4 * q + 0) * 132 + row] = pa[i].x;
            As[(4 * q + 1) * 132 + row] = pa[i].y;
            As[(4 * q + 2) * 132 + row] = pa[i].z;
            As[(4 * q + 3) * 132 + row] = pa[i].w;
            const int c4 = id & 31, k = id >> 5;
            *(float4*)(Bs + k * 132 + 4 * c4) = pb[i];
        }
        __syncthreads();
        if (kk0 + 16 < 256) {                       // prefetch next tiles
#pragma unroll
            for (int i = 0; i < 2; ++i) {
                const int id = threadIdx.x + 256 * i;
                pa[i] = *(const float4*)(A + (size_t)(m0 + (id >> 2)) * 256 +
                                         kk0 + 16 + 4 * (id & 3));
                pb[i] = *(const float4*)(W + (size_t)(kk0 + 16 + (id >> 5)) * 1024 +
                                         c0 + 4 * (id & 31));
            }
        }
#pragma unroll
        for (int kk = 0; kk < 16; ++kk) {
            const float4 a0 = *(const float4*)(As + kk * 132 + 4 * ty);
            const float4 a1 = *(const float4*)(As + kk * 132 + 64 + 4 * ty);
            const ulonglong2 bq0 = *(const ulonglong2*)(Bs + kk * 132 + 4 * tx);
            const ulonglong2 bq1 = *(const ulonglong2*)(Bs + kk * 132 + 64 + 4 * tx);
            const float av[8] = {a0.x, a0.y, a0.z, a0.w, a1.x, a1.y, a1.z, a1.w};
#pragma unroll
            for (int i = 0; i < 8; ++i) {
                const unsigned long long ad = pack2(av[i]);
                ffma2(acc2[i][0], ad, bq0.x);
                ffma2(acc2[i][1], ad, bq0.y);
                ffma2(acc2[i][2], ad, bq1.x);
                ffma2(acc2[i][3], ad, bq1.y);
            }
        }
        __syncthreads();
    }
#pragma unroll
    for (int i = 0; i < 8; ++i) {
        const int row = (i < 4) ? (4 * ty + i) : (64 + 4 * ty + (i - 4));
        float* p = g_P + (size_t)(m0 + row) * 1024 + c0;
        float4 o0, o1;
        float lo, hi;
        unpack2(acc2[i][0], lo, hi);
        o0.x = lo + bias[c0 + 4 * tx + 0];
        o0.y = hi + bias[c0 + 4 * tx + 1];
        unpack2(acc2[i][1], lo, hi);
        o0.z = lo + bias[c0 + 4 * tx + 2];
        o0.w = hi + bias[c0 + 4 * tx + 3];
        unpack2(acc2[i][2], lo, hi);
        o1.x = lo + bias[c0 + 64 + 4 * tx + 0];
        o1.y = hi + bias[c0 + 64 + 4 * tx + 1];
        unpack2(acc2[i][3], lo, hi);
        o1.z = lo + bias[c0 + 64 + 4 * tx + 2];
        o1.w = hi + bias[c0 + 64 + 4 * tx + 3];
        *(float4*)(p + 4 * tx) = o0;
        *(float4*)(p + 64 + 4 * tx) = o1;
    }
}

// ---------------------------------------------------------------------------
// K4 v6: LSTM recurrence — bulk DSMEM h-exchange (8 tx/step, not 2048).
// 16 clusters x 8 CTAs; cluster owns 8 batches; CTA rank owns 32 hidden units.
// 512 threads, 4-way k-split; U in registers; broadcast h loads.
// h buffers rank-blocked: hb2[buf][rank][b*32+u]. Owners stage their 1KB h
// slice locally; 8 threads issue 8 x cp.async.bulk (1KB) to all CTAs with
// remote-mbarrier complete_tx. No cluster.sync in the loop.
// ---------------------------------------------------------------------------
#define PITCH 260
#define UT_FLOATS (128 * PITCH)              // 33280 (U staging, 130 KB)
#define HB2_OFF   UT_FLOATS                  // 2 x 2048 floats
#define STAGE_OFF (HB2_OFF + 4096)           // 2 x 256 floats
#define REDA_OFF  (STAGE_OFF + 512)          // float4[512]
#define REDB_OFF  (REDA_OFF + 2048)          // float4[512]
#define MBAR_OFF  (REDB_OFF + 2048)          // 2 x u64
#define SMEM_FLOATS (MBAR_OFF + 4)           // 41988
#define SMEM_BYTES  (SMEM_FLOATS * 4)        // 167,952 B
#define TX_PER_STEP (8 * 1024)               // 8 ranks x 1KB into each CTA

__global__ __launch_bounds__(512, 1) __cluster_dims__(8, 1, 1)
void k_lstm(const float* __restrict__ X, const float* __restrict__ U,
            float* __restrict__ out_enc) {
    extern __shared__ float sm[];
    float* Ut    = sm;                        // [128 gate-cols][k, pitch 260]
    float* hb2   = sm + HB2_OFF;              // 2 x [8 ranks][256]
    float* stage = sm + STAGE_OFF;            // 2 x [256]
    float4* redA = (float4*)(sm + REDA_OFF);  // [4 KQ][128 col] batches 0..3
    float4* redB = (float4*)(sm + REDB_OFF);  // [4 KQ][128 col] batches 4..7

    cg::cluster_group cl = cg::this_cluster();
    const int rank = (int)cl.block_rank();           // 0..7
    const int b0   = (blockIdx.x >> 3) * 8;
    const int tid  = threadIdx.x;
    // compute role
    const int col  = tid & 127;                      // gate-col 0..127
    const int KQ   = tid >> 7;                       // k quarter 0..3
    // owner role (tid < 256)
    const int ob   = tid >> 5;                       // batch 0..7
    const int ou   = tid & 31;                       // unit 0..31
    const int jglob = rank * 32 + ou;

    const uint32_t smb = smem_u32(sm);
    const uint32_t mbar0 = smb + MBAR_OFF * 4;       // mbar[i] at +8*i

    // Stage U slice: Ut[(g*32+jr)*PITCH + k] = U[k*1024 + g*256 + rank*32 + jr]
    for (int idx = tid; idx < 128 * 256; idx += 512) {
        const int k = idx >> 7;
        const int cr = idx & 127;
        const int g = cr >> 5, jr = cr & 31;
        Ut[cr * PITCH + k] = U[(size_t)k * 1024 + g * 256 + rank * 32 + jr];
    }
    // h0 = c0 = X[b,0,0]; fill buffer 0 locally. Layout [r][b*32+u].
    for (int idx = tid; idx < 2048; idx += 512) {
        const int b = (idx >> 5) & 7;
        hb2[idx] = X[(size_t)(b0 + b) * TT * NN];
    }
    if (tid == 0) {
        mbar_init(mbar0 + 0, 1);
        mbar_init(mbar0 + 8, 1);
        mbar_arm_tx(mbar0 + 0, TX_PER_STEP);   // first waited at t=2
        mbar_arm_tx(mbar0 + 8, TX_PER_STEP);   // first waited at t=1
    }
    __syncthreads();

    // Pull this thread's U quarter into registers: 64 floats = 16 ulonglong2
    ulonglong2 u2[16];
    {
        const float* ub = Ut + col * PITCH + KQ * 64;
#pragma unroll
        for (int i = 0; i < 16; ++i) u2[i] = *(const ulonglong2*)(ub + 4 * i);
    }
    float c = (tid < 256) ? X[(size_t)(b0 + ob) * TT * NN] : 0.0f;
    cl.sync();   // mbarriers + buffer0 visible cluster-wide (once)

    const float* Pb = g_P + ((size_t)(b0 + ob) * TT) * 1024 + jglob;
    float* Ob = out_enc + ((size_t)(b0 + ob) * TT) * HH + jglob;
    float pi = 0.f, pf = 0.f, pg = 0.f, po = 0.f;
    if (tid < 256) { pi = Pb[0]; pf = Pb[256]; pg = Pb[512]; po = Pb[768]; }

    uint32_t ph0 = 0, ph1 = 0;

    for (int t = 0; t < TT; ++t) {
        const int cb = t & 1;
        // prefetch next-step P before the wait (DRAM latency overlaps barrier)
        float npi = 0.f, npf = 0.f, npg = 0.f, npo = 0.f;
        if (tid < 256 && t + 1 < TT) {
            const float* pr = Pb + (size_t)(t + 1) * 1024;
            npi = pr[0]; npf = pr[256]; npg = pr[512]; npo = pr[768];
        }
        if (t > 0) {
            const uint32_t mb = mbar0 + 8 * cb;
            if (cb) { mbar_wait_acq(mb, ph1); ph1 ^= 1; }
            else    { mbar_wait_acq(mb, ph0); ph0 ^= 1; }
            if (tid == 0 && t + 2 < TT) mbar_arm_tx(mb, TX_PER_STEP);
        }

        const float* hbase = hb2 + cb * 2048;        // [r][b*32+u]
        unsigned long long acc[8];
#pragma unroll
        for (int b = 0; b < 8; ++b) acc[b] = 0ull;

#pragma unroll
        for (int ch = 0; ch < 16; ++ch) {
            const int k0 = KQ * 64 + 4 * ch;
            const float* ha = hbase + ((k0 >> 5) << 8) + (k0 & 31);
            const ulonglong2 uv = u2[ch];
#pragma unroll
            for (int b = 0; b < 8; ++b) {
                const ulonglong2 hv = *(const ulonglong2*)(ha + 32 * b);
                ffma2(acc[b], hv.x, uv.x);
                ffma2(acc[b], hv.y, uv.y);
            }
        }

        float4 r0, r1;
        r0.x = pairsum(acc[0]); r0.y = pairsum(acc[1]);
        r0.z = pairsum(acc[2]); r0.w = pairsum(acc[3]);
        r1.x = pairsum(acc[4]); r1.y = pairsum(acc[5]);
        r1.z = pairsum(acc[6]); r1.w = pairsum(acc[7]);
        redA[KQ * 128 + col] = r0;
        redB[KQ * 128 + col] = r1;
        __syncthreads();

        if (tid < 256) {
            // owner phase: combine 4 k-quarter partials, component = ob
            const float* ra = (const float*)((ob < 4) ? redA : redB);
            const int comp = ob & 3;
            float si = 0.f, sf = 0.f, sg = 0.f, so = 0.f;
#pragma unroll
            for (int q = 0; q < 4; ++q) {
                const int base = q * 128 * 4;
                si += ra[base + (0  + ou) * 4 + comp];
                sf += ra[base + (32 + ou) * 4 + comp];
                sg += ra[base + (64 + ou) * 4 + comp];
                so += ra[base + (96 + ou) * 4 + comp];
            }
            const float gi = sigf(pi + si);
            const float gf = sigf(pf + sf);
            const float gg = tanh_fast(pg + sg);
            const float go = sigf(po + so);
            c = gf * c + gi * gg;
            const float h = go * tanh_fast(c);

            Ob[(size_t)t * HH] = h;

            if (t + 1 < TT) {
                // stage local h slice (double-buffered by cb), then bulk-send
                stage[cb * 256 + ob * 32 + ou] = h;
                asm volatile("bar.sync 1, 256;" ::: "memory");
                if (tid < 8) {
                    fence_async_proxy();
                    const int nb = 1 - cb;
                    const uint32_t src = smb + (STAGE_OFF + cb * 256) * 4;
                    const uint32_t dstl = smb +
                        (HB2_OFF + nb * 2048 + rank * 256) * 4;
                    const uint32_t lmbar = mbar0 + 8 * nb;
                    const uint32_t r2 = (uint32_t)tid;
                    bulk_dsmem(mapa_u32(dstl, r2), src, 1024,
                               mapa_u32(lmbar, r2));
                }
            }
            pi = npi; pf = npf; pg = npg; po = npo;
        }
    }
    cl.sync();   // teardown safety
}

// ---------------------------------------------------------------------------
extern "C" void kernel_launch(void* const* d_in, const int* in_sizes, int n_in,
                              void* d_out, int out_size) {
    const float* X  = (const float*)d_in[0];
    const float* Wa = (const float*)d_in[1];
    const float* ba = (const float*)d_in[2];
    const float* Wl = (const float*)d_in[3];
    const float* Ul = (const float*)d_in[4];
    const float* bl = (const float*)d_in[5];
    float* out = (float*)d_out;
    float* out_xt  = out;                          // (B,Tm1,N)
    float* out_enc = out + (size_t)MM * NN;        // (B,Tm1,H)

    cudaFuncSetAttribute(k_lstm, cudaFuncAttributeMaxDynamicSharedMemorySize,
                         SMEM_BYTES);

    k_alpha<<<BB, 256>>>(X, Wa, ba);
    k_xtilde<<<(MM * NN / 4) / 256, 256>>>(X, out_xt);
    k_gemm<<<dim3(FH / 128, MM / 128), 256>>>(out_xt, Wl, bl);
    k_lstm<<<128, 512, SMEM_BYTES>>>(X, Ul, out_enc);
}